// round 16
// baseline (speedup 1.0000x reference)
#include <cuda_runtime.h>
#include <cuda_fp16.h>
#include <cstdint>
#include <cstddef>

#define NROWS   8192
#define DHEAD   256
#define BM      64
#define BN      64
#define SSTRIDE 268          // fp32 K pitch: 1072B ≡ 48 (mod 128) ldmatrix-safe; ≡12 (mod 32) scalar-safe
#define KHP     264          // f16 K pitch in halves: 528B ≡ 16 (mod 128) -> ldmatrix conflict-free
#define KHPB    528
#define PSTR    68           // P-buffer pitch: 272B ≡ 16 (mod 128) ldmatrix conflict-free
#define KSZ     (BN * SSTRIDE)
#define KHSZF   (BN * KHP / 2)       // f16 plane size in floats
#define PSZ     (BM * PSTR)
#define THREADS 256
#define LOG2E   1.4426950408889634f
#define CEXP2   126.95716359822878f  // 88 * log2(e): softmax offset in log2 domain

// Static scratch: f16 planes of M (keys/values) and N (queries, hi+lo split, pre-scaled by log2e).
__device__ static __half g_Mh[NROWS * DHEAD];
__device__ static __half g_Qh[NROWS * DHEAD];
__device__ static __half g_Ql[NROWS * DHEAD];

// tf32 MMA: D(16x8) += A(16x8) * B(8x8), raw b32 operands.
__device__ __forceinline__ void mma8u(float* c, unsigned a0, unsigned a1, unsigned a2,
                                      unsigned a3, unsigned b0, unsigned b1) {
    asm volatile(
        "mma.sync.aligned.m16n8k8.row.col.f32.tf32.tf32.f32 "
        "{%0,%1,%2,%3}, {%4,%5,%6,%7}, {%8,%9}, {%0,%1,%2,%3};\n"
        : "+f"(c[0]), "+f"(c[1]), "+f"(c[2]), "+f"(c[3])
        : "r"(a0), "r"(a1), "r"(a2), "r"(a3), "r"(b0), "r"(b1));
}

// f16 MMA: D(16x8) += A(16x16) * B(16x8), fp32 accumulate.
__device__ __forceinline__ void mma16(float* c, const unsigned* a, unsigned b0, unsigned b1) {
    asm volatile(
        "mma.sync.aligned.m16n8k16.row.col.f32.f16.f16.f32 "
        "{%0,%1,%2,%3}, {%4,%5,%6,%7}, {%8,%9}, {%0,%1,%2,%3};\n"
        : "+f"(c[0]), "+f"(c[1]), "+f"(c[2]), "+f"(c[3])
        : "r"(a[0]), "r"(a[1]), "r"(a[2]), "r"(a[3]), "r"(b0), "r"(b1));
}

__device__ __forceinline__ void ldsm4(unsigned addr, unsigned& r0, unsigned& r1,
                                      unsigned& r2, unsigned& r3) {
    asm volatile("ldmatrix.sync.aligned.m8n8.x4.shared.b16 {%0,%1,%2,%3}, [%4];\n"
                 : "=r"(r0), "=r"(r1), "=r"(r2), "=r"(r3) : "r"(addr));
}

__device__ __forceinline__ void cpa16(void* s, const void* g) {
    unsigned sa = (unsigned)__cvta_generic_to_shared(s);
    asm volatile("cp.async.cg.shared.global [%0], [%1], 16;\n" :: "r"(sa), "l"(g));
}
__device__ __forceinline__ void cpa_commit() { asm volatile("cp.async.commit_group;\n"); }
__device__ __forceinline__ void cpa_wait0()  { asm volatile("cp.async.wait_group 0;\n" ::: "memory"); }
__device__ __forceinline__ void cpa_wait1()  { asm volatile("cp.async.wait_group 1;\n" ::: "memory"); }

// One-time conversion: M -> f16; N -> (N*log2e) f16 hi + f16 lo (residual).
__global__ void convert_kernel(const float* __restrict__ Mm, const float* __restrict__ Nm,
                               int total) {
    int i = (blockIdx.x * blockDim.x + threadIdx.x) * 2;
    if (i >= total) return;
    float2 m = *(const float2*)(Mm + i);
    *(__half2*)(g_Mh + i) = __floats2half2_rn(m.x, m.y);
    float2 q = *(const float2*)(Nm + i);
    q.x *= LOG2E; q.y *= LOG2E;
    __half2 qh = __floats2half2_rn(q.x, q.y);
    *(__half2*)(g_Qh + i) = qh;
    *(__half2*)(g_Ql + i) = __floats2half2_rn(q.x - __half2float(__low2half(qh)),
                                              q.y - __half2float(__high2half(qh)));
}

__global__ __launch_bounds__(THREADS, 1)
void attn_matcher_kernel(const float* __restrict__ Mm, const float* __restrict__ Nm,
                         const float* __restrict__ Wg, const float* __restrict__ bgp,
                         const float* __restrict__ gbp, const int* __restrict__ isev,
                         float* __restrict__ out, int nrows)
{
    extern __shared__ float sm[];
    float*  kb0   = sm;                      // [BN][SSTRIDE] fp32 K/V tile buf 0
    float*  kb1   = kb0 + KSZ;               // [BN][SSTRIDE] fp32 buf 1 (Qh/Ql staged here first)
    __half* kh0   = (__half*)(kb1 + KSZ);    // [BN][KHP]     f16 K tile buf 0
    __half* kh1   = kh0 + BN * KHP;          // [BN][KHP]     f16 K tile buf 1
    float*  Pb    = (float*)(kh1 + BN * KHP);// [BM][PSTR]    P exchange buffer
    float*  wgs   = Pb + PSZ;                // [DHEAD]       gate weights
    float*  lpart = wgs + DHEAD;             // [2][BM]       per-row l partials (by hf)
    float*  gpart = lpart + 2 * BM;          // [8][BM]       per-row gate partials (by warp)

    const int tid   = threadIdx.x;
    const int lane  = tid & 31;
    const int warp  = tid >> 5;
    const int strip = warp & 3;              // GEMM1: query strip (16 rows)
    const int hf    = warp >> 2;             // GEMM1: key half (0: keys 0-31, 1: 32-63)
    const int qr    = lane >> 2;
    const int qc    = lane & 3;
    const int qbase = blockIdx.x * BM;

    // ---- stage Qh/Ql f16 planes into kb1 (group 1) ----
    __half* qstage = (__half*)kb1;
    for (int i = tid; i < BM * 32; i += THREADS) {       // 32 x 16B chunks per row
        int r = i >> 5, c = i & 31;
        cpa16(qstage + r * KHP + c * 8,            g_Qh + (size_t)(qbase + r) * DHEAD + c * 8);
        cpa16(qstage + BM * KHP + r * KHP + c * 8, g_Ql + (size_t)(qbase + r) * DHEAD + c * 8);
    }
    cpa_commit();
    // ---- prefetch key tile 0: fp32 -> kb0, f16 -> kh0 (group 2) ----
    for (int i = tid; i < BN * 64; i += THREADS) {
        int r = i >> 6, c = i & 63;
        cpa16(kb0 + r * SSTRIDE + c * 4, Mm + (size_t)r * DHEAD + c * 4);
    }
    for (int i = tid; i < BN * 32; i += THREADS) {
        int r = i >> 5, c = i & 31;
        cpa16(kh0 + r * KHP + c * 8, g_Mh + (size_t)r * DHEAD + c * 8);
    }
    cpa_commit();
    for (int i = tid; i < DHEAD; i += THREADS) wgs[i] = Wg[i];

    const bool evalmode = (isev[0] != 0);
    const int grow0 = qbase + strip * 16 + qr;
    const int grow1 = grow0 + 8;
    const float C0 = (evalmode && grow0 == 0) ? 0.f : CEXP2;  // eval row 0: s==0 -> P=1 exactly

    const int lg = lane >> 3;
    const int lr = lane & 7;
    unsigned kb1_sh = (unsigned)__cvta_generic_to_shared(kb1);
    unsigned kh0_sh = (unsigned)__cvta_generic_to_shared(kh0);
    unsigned kh1_sh = (unsigned)__cvta_generic_to_shared(kh1);
    unsigned Pb_sh  = (unsigned)__cvta_generic_to_shared(Pb);
    unsigned aBrow  = (hf * 32 + lr) * KHPB + lg * 16u;       // f16 K-frag row base

    // ---- wait for Q planes (group 1), build resident f16 A-frags (hi + lo) ----
    cpa_wait1();
    __syncthreads();
    unsigned aregH[16][4], aregL[16][4];     // 16 k16-chunks x 4 regs x 2 planes = 128 regs
    {
        unsigned base = kb1_sh + (strip * 16 + (lg & 1) * 8 + lr) * KHPB + (lg >> 1) * 16u;
        #pragma unroll
        for (int j = 0; j < 16; j++)
            ldsm4(base + j * 32u, aregH[j][0], aregH[j][1], aregH[j][2], aregH[j][3]);
        base += BM * KHPB;                   // Ql plane offset
        #pragma unroll
        for (int j = 0; j < 16; j++)
            ldsm4(base + j * 32u, aregL[j][0], aregL[j][1], aregL[j][2], aregL[j][3]);
    }

    // O accumulator: warp owns O[all 64 rows][n-slice warp*32 .. +32)
    float o[4][4][4];
    #pragma unroll
    for (int mt = 0; mt < 4; mt++)
        #pragma unroll
        for (int nt = 0; nt < 4; nt++)
            { o[mt][nt][0]=0.f; o[mt][nt][1]=0.f; o[mt][nt][2]=0.f; o[mt][nt][3]=0.f; }
    float l0 = 0.f, l1 = 0.f;                // per-lane partial row sums (reduced in epilogue)

    const int ntiles = nrows / BN;

    for (int jb = 0; jb < ntiles; jb++) {
        cpa_wait0();
        __syncthreads();                     // tile jb ready; prev tile fully consumed
        float* kb = (jb & 1) ? kb1 : kb0;
        unsigned kh_sh = (jb & 1) ? kh1_sh : kh0_sh;

        if (jb + 1 < ntiles) {               // prefetch next tile -> other buffers
            float*  kn  = (jb & 1) ? kb0 : kb1;
            __half* khn = (jb & 1) ? kh0 : kh1;
            const float*  src  = Mm   + (size_t)(jb + 1) * BN * DHEAD;
            const __half* srcH = g_Mh + (size_t)(jb + 1) * BN * DHEAD;
            for (int i = tid; i < BN * 64; i += THREADS) {
                int r = i >> 6, c = i & 63;
                cpa16(kn + r * SSTRIDE + c * 4, src + (size_t)r * DHEAD + c * 4);
            }
            for (int i = tid; i < BN * 32; i += THREADS) {
                int r = i >> 5, c = i & 31;
                cpa16(khn + r * KHP + c * 8, srcH + (size_t)r * DHEAD + c * 8);
            }
            cpa_commit();
        }

        // ---- GEMM1 (f16, 2-term): S'[strip rows][hf keys] = (Qh+Ql) . Kh^T  (log2 domain) ----
        float s[4][4];
        #pragma unroll
        for (int t = 0; t < 4; t++) { s[t][0]=0.f; s[t][1]=0.f; s[t][2]=0.f; s[t][3]=0.f; }
        unsigned aB = kh_sh + aBrow;
        #pragma unroll
        for (int jj = 0; jj < 8; jj++) {     // 32 dims (2 k16 chunks) per step
            #pragma unroll
            for (int t = 0; t < 4; t++) {
                unsigned b0, b1, b2, b3;
                ldsm4(aB + t * (8u * KHPB) + jj * 64u, b0, b1, b2, b3);
                mma16(s[t], aregH[2*jj],   b0, b1);
                mma16(s[t], aregL[2*jj],   b0, b1);
                mma16(s[t], aregH[2*jj+1], b2, b3);
                mma16(s[t], aregL[2*jj+1], b2, b3);
            }
        }

        // ---- mask (training: zero diag; eval: zero query row 0) ----
        int colbase = jb * BN + hf * 32 + 2 * qc;
        if (!evalmode) {
            #pragma unroll
            for (int t = 0; t < 4; t++) {
                int c0 = colbase + t * 8;
                if (c0     == grow0) s[t][0] = 0.f;
                if (c0 + 1 == grow0) s[t][1] = 0.f;
                if (c0     == grow1) s[t][2] = 0.f;
                if (c0 + 1 == grow1) s[t][3] = 0.f;
            }
        } else if (grow0 == 0) {
            #pragma unroll
            for (int t = 0; t < 4; t++) { s[t][0] = 0.f; s[t][1] = 0.f; }
        }

        // ---- P = exp2(s' - C), accumulate per-lane row-sum partials (no shuffles) ----
        #pragma unroll
        for (int t = 0; t < 4; t++) {
            s[t][0] = exp2f(s[t][0] - C0);
            s[t][1] = exp2f(s[t][1] - C0);
            s[t][2] = exp2f(s[t][2] - CEXP2);
            s[t][3] = exp2f(s[t][3] - CEXP2);
            l0 += s[t][0] + s[t][1];
            l1 += s[t][2] + s[t][3];
        }

        // ---- write P to exchange buffer ----
        {
            float* pr0 = Pb + (strip * 16 + qr) * PSTR + hf * 32 + 2 * qc;
            float* pr1 = pr0 + 8 * PSTR;
            #pragma unroll
            for (int t = 0; t < 4; t++) {
                *(float2*)(pr0 + t * 8) = make_float2(s[t][0], s[t][1]);
                *(float2*)(pr1 + t * 8) = make_float2(s[t][2], s[t][3]);
            }
        }
        __syncthreads();                     // P complete for all 64 rows x 64 keys

        // ---- GEMM2 (tf32): O[64 rows][warp n-slice 32] += P . V  (lo/hi k8-halves) ----
        const unsigned* kbu = (const unsigned*)kb;
        unsigned aP = Pb_sh + (((lg & 1) * 8 + lr) * PSTR) * 4u + (lg >> 1) * 16u;
        #pragma unroll
        for (int kp = 0; kp < 4; kp++) {     // 16 keys per step
            #pragma unroll
            for (int h = 0; h < 2; h++) {    // k8 half: keys kp*16+8h .. +8
                unsigned vv[4][2];
                int krow = kp * 16 + h * 8 + qc;
                #pragma unroll
                for (int nt = 0; nt < 4; nt++) {
                    int col = warp * 32 + nt * 8 + qr;
                    vv[nt][0] = kbu[krow       * SSTRIDE + col];
                    vv[nt][1] = kbu[(krow + 4) * SSTRIDE + col];
                }
                #pragma unroll
                for (int mt = 0; mt < 4; mt++) {
                    unsigned p0, p1, p2, p3;
                    ldsm4(aP + mt * (16u * PSTR * 4u) + kp * 64u + h * 32u, p0, p1, p2, p3);
                    #pragma unroll
                    for (int nt = 0; nt < 4; nt++)
                        mma8u(o[mt][nt], p0, p1, p2, p3, vv[nt][0], vv[nt][1]);
                }
            }
        }
    }

    // ---- epilogue ----
    __syncthreads();
    l0 += __shfl_xor_sync(0xffffffffu, l0, 1);
    l0 += __shfl_xor_sync(0xffffffffu, l0, 2);
    l1 += __shfl_xor_sync(0xffffffffu, l1, 1);
    l1 += __shfl_xor_sync(0xffffffffu, l1, 2);
    if (qc == 0) {
        lpart[hf * BM + strip * 16 + qr]     = l0;
        lpart[hf * BM + strip * 16 + qr + 8] = l1;
    }
    __syncthreads();

    float gp[4][2];
    #pragma unroll
    for (int mt = 0; mt < 4; mt++) {
        int r0 = mt * 16 + qr, r1 = r0 + 8;
        float inv0 = 1.f / (lpart[r0] + lpart[BM + r0]);
        float inv1 = 1.f / (lpart[r1] + lpart[BM + r1]);
        float g0 = 0.f, g1 = 0.f;
        #pragma unroll
        for (int nt = 0; nt < 4; nt++) {
            int c0 = warp * 32 + nt * 8 + 2 * qc;
            o[mt][nt][0] *= inv0; o[mt][nt][1] *= inv0;
            o[mt][nt][2] *= inv1; o[mt][nt][3] *= inv1;
            g0 += o[mt][nt][0] * wgs[c0] + o[mt][nt][1] * wgs[c0 + 1];
            g1 += o[mt][nt][2] * wgs[c0] + o[mt][nt][3] * wgs[c0 + 1];
        }
        g0 += __shfl_xor_sync(0xffffffffu, g0, 1);
        g0 += __shfl_xor_sync(0xffffffffu, g0, 2);
        g1 += __shfl_xor_sync(0xffffffffu, g1, 1);
        g1 += __shfl_xor_sync(0xffffffffu, g1, 2);
        gp[mt][0] = g0; gp[mt][1] = g1;
    }
    if (qc == 0) {
        #pragma unroll
        for (int mt = 0; mt < 4; mt++) {
            gpart[warp * BM + mt * 16 + qr]     = gp[mt][0];
            gpart[warp * BM + mt * 16 + qr + 8] = gp[mt][1];
        }
    }
    __syncthreads();

    float gb = bgp[0] + gbp[0];
    #pragma unroll
    for (int mt = 0; mt < 4; mt++) {
        int r0 = mt * 16 + qr, r1 = r0 + 8;
        float sg0 = 0.f, sg1 = 0.f;
        #pragma unroll
        for (int ww = 0; ww < 8; ww++) { sg0 += gpart[ww * BM + r0]; sg1 += gpart[ww * BM + r1]; }
        float gate0 = 1.f / (1.f + __expf(-(sg0 + gb)));
        float gate1 = 1.f / (1.f + __expf(-(sg1 + gb)));
        float* orow0 = out + (size_t)(qbase + r0) * DHEAD;
        float* orow1 = out + (size_t)(qbase + r1) * DHEAD;
        const float* nrow0 = Nm + (size_t)(qbase + r0) * DHEAD;
        const float* nrow1 = Nm + (size_t)(qbase + r1) * DHEAD;
        #pragma unroll
        for (int nt = 0; nt < 4; nt++) {
            int c0 = warp * 32 + nt * 8 + 2 * qc;
            float2 nres0 = *(const float2*)(nrow0 + c0);
            float2 nres1 = *(const float2*)(nrow1 + c0);
            float2 w0, w1;
            w0.x = o[mt][nt][0] * gate0 + nres0.x * (1.f - gate0);
            w0.y = o[mt][nt][1] * gate0 + nres0.y * (1.f - gate0);
            w1.x = o[mt][nt][2] * gate1 + nres1.x * (1.f - gate1);
            w1.y = o[mt][nt][3] * gate1 + nres1.y * (1.f - gate1);
            *(float2*)(orow0 + c0) = w0;
            *(float2*)(orow1 + c0) = w1;
        }
    }
}

extern "C" void kernel_launch(void* const* d_in, const int* in_sizes, int n_in,
                              void* d_out, int out_size) {
    const float* Mm  = (const float*)d_in[0];
    const float* Nm  = (const float*)d_in[1];
    const float* Wg  = (const float*)d_in[2];
    const float* bg  = (const float*)d_in[3];
    const float* gbv = (const float*)d_in[4];
    const int*   ise = (const int*)  d_in[5];
    int nrows = in_sizes[0] / DHEAD;                      // 8192
    int total = nrows * DHEAD;

    convert_kernel<<<(total / 2 + 255) / 256, 256>>>(Mm, Nm, total);

    size_t smem = (size_t)(2 * KSZ + 2 * KHSZF + PSZ + DHEAD + 2 * BM + 8 * BM)
                  * sizeof(float);                        // ~220.5 KB
    cudaFuncSetAttribute(attn_matcher_kernel,
                         cudaFuncAttributeMaxDynamicSharedMemorySize, (int)smem);
    attn_matcher_kernel<<<nrows / BM, THREADS, smem>>>(Mm, Nm, Wg, bg, gbv, ise,
                                                       (float*)d_out, nrows);
}

// round 17
// speedup vs baseline: 1.5803x; 1.5803x over previous
#include <cuda_runtime.h>
#include <cuda_fp16.h>
#include <cstdint>
#include <cstddef>

#define NROWS   8192
#define DHEAD   256
#define BM      64
#define BN      64
#define SSTRIDE 268          // fp32 K pitch: 1072B ≡ 48 (mod 128) ldmatrix-safe; ≡12 (mod 32) scalar-safe
#define KHP     264          // f16 K pitch in halves: 528B ≡ 16 (mod 128) -> ldmatrix conflict-free
#define KHPB    528
#define PSTR    68           // P-buffer pitch: 272B ≡ 16 (mod 128) ldmatrix conflict-free
#define KSZ     (BN * SSTRIDE)
#define KHSZF   (BN * KHP / 2)       // f16 plane size in floats
#define PSZ     (BM * PSTR)
#define THREADS 256
#define LOG2E   1.4426950408889634f
#define CEXP2   126.95716359822878f  // 88 * log2(e): softmax offset in log2 domain

// Static scratch: f16 planes of M (keys/values) and N (queries, hi+lo split, pre-scaled by log2e).
__device__ static __half g_Mh[NROWS * DHEAD];
__device__ static __half g_Qh[NROWS * DHEAD];
__device__ static __half g_Ql[NROWS * DHEAD];

// tf32 MMA: D(16x8) += A(16x8) * B(8x8), raw b32 operands.
__device__ __forceinline__ void mma8u(float* c, unsigned a0, unsigned a1, unsigned a2,
                                      unsigned a3, unsigned b0, unsigned b1) {
    asm volatile(
        "mma.sync.aligned.m16n8k8.row.col.f32.tf32.tf32.f32 "
        "{%0,%1,%2,%3}, {%4,%5,%6,%7}, {%8,%9}, {%0,%1,%2,%3};\n"
        : "+f"(c[0]), "+f"(c[1]), "+f"(c[2]), "+f"(c[3])
        : "r"(a0), "r"(a1), "r"(a2), "r"(a3), "r"(b0), "r"(b1));
}

// f16 MMA: D(16x8) += A(16x16) * B(16x8), fp32 accumulate.
__device__ __forceinline__ void mma16(float* c, const unsigned* a, unsigned b0, unsigned b1) {
    asm volatile(
        "mma.sync.aligned.m16n8k16.row.col.f32.f16.f16.f32 "
        "{%0,%1,%2,%3}, {%4,%5,%6,%7}, {%8,%9}, {%0,%1,%2,%3};\n"
        : "+f"(c[0]), "+f"(c[1]), "+f"(c[2]), "+f"(c[3])
        : "r"(a[0]), "r"(a[1]), "r"(a[2]), "r"(a[3]), "r"(b0), "r"(b1));
}

__device__ __forceinline__ void ldsm4(unsigned addr, unsigned& r0, unsigned& r1,
                                      unsigned& r2, unsigned& r3) {
    asm volatile("ldmatrix.sync.aligned.m8n8.x4.shared.b16 {%0,%1,%2,%3}, [%4];\n"
                 : "=r"(r0), "=r"(r1), "=r"(r2), "=r"(r3) : "r"(addr));
}

__device__ __forceinline__ void cpa16(void* s, const void* g) {
    unsigned sa = (unsigned)__cvta_generic_to_shared(s);
    asm volatile("cp.async.cg.shared.global [%0], [%1], 16;\n" :: "r"(sa), "l"(g));
}
__device__ __forceinline__ void cpa_commit() { asm volatile("cp.async.commit_group;\n"); }
__device__ __forceinline__ void cpa_wait0()  { asm volatile("cp.async.wait_group 0;\n" ::: "memory"); }
__device__ __forceinline__ void cpa_wait1()  { asm volatile("cp.async.wait_group 1;\n" ::: "memory"); }

// One-time conversion: M -> f16; N -> (N*log2e) f16 hi + f16 lo (residual).
__global__ void convert_kernel(const float* __restrict__ Mm, const float* __restrict__ Nm,
                               int total) {
    int i = (blockIdx.x * blockDim.x + threadIdx.x) * 2;
    if (i >= total) return;
    float2 m = *(const float2*)(Mm + i);
    *(__half2*)(g_Mh + i) = __floats2half2_rn(m.x, m.y);
    float2 q = *(const float2*)(Nm + i);
    q.x *= LOG2E; q.y *= LOG2E;
    __half2 qh = __floats2half2_rn(q.x, q.y);
    *(__half2*)(g_Qh + i) = qh;
    *(__half2*)(g_Ql + i) = __floats2half2_rn(q.x - __half2float(__low2half(qh)),
                                              q.y - __half2float(__high2half(qh)));
}

__global__ __launch_bounds__(THREADS, 1)
void attn_matcher_kernel(const float* __restrict__ Mm, const float* __restrict__ Nm,
                         const float* __restrict__ Wg, const float* __restrict__ bgp,
                         const float* __restrict__ gbp, const int* __restrict__ isev,
                         float* __restrict__ out, int nrows)
{
    extern __shared__ float sm[];
    float*  kb0   = sm;                      // [BN][SSTRIDE] fp32 K/V tile buf 0
    float*  kb1   = kb0 + KSZ;               // [BN][SSTRIDE] fp32 buf 1 (Qh/Ql staged here first)
    __half* kh0   = (__half*)(kb1 + KSZ);    // [BN][KHP]     f16 K tile buf 0
    __half* kh1   = kh0 + BN * KHP;          // [BN][KHP]     f16 K tile buf 1
    float*  Pb    = (float*)(kh1 + BN * KHP);// [BM][PSTR]    P exchange buffer
    float*  wgs   = Pb + PSZ;                // [DHEAD]       gate weights
    float*  lpart = wgs + DHEAD;             // [2][BM]       per-row l partials (by hf)
    float*  gpart = lpart + 2 * BM;          // [8][BM]       per-row gate partials (by warp)

    const int tid   = threadIdx.x;
    const int lane  = tid & 31;
    const int warp  = tid >> 5;
    const int strip = warp & 3;              // GEMM1: query strip (16 rows)
    const int hf    = warp >> 2;             // GEMM1: key half (0: keys 0-31, 1: 32-63)
    const int qr    = lane >> 2;
    const int qc    = lane & 3;
    const int qbase = blockIdx.x * BM;

    // ---- stage Qh/Ql f16 planes into kb1 (group 1) ----
    __half* qstage = (__half*)kb1;
    for (int i = tid; i < BM * 32; i += THREADS) {       // 32 x 16B chunks per row
        int r = i >> 5, c = i & 31;
        cpa16(qstage + r * KHP + c * 8,            g_Qh + (size_t)(qbase + r) * DHEAD + c * 8);
        cpa16(qstage + BM * KHP + r * KHP + c * 8, g_Ql + (size_t)(qbase + r) * DHEAD + c * 8);
    }
    cpa_commit();
    // ---- prefetch key tile 0: fp32 -> kb0, f16 -> kh0 (group 2) ----
    for (int i = tid; i < BN * 64; i += THREADS) {
        int r = i >> 6, c = i & 63;
        cpa16(kb0 + r * SSTRIDE + c * 4, Mm + (size_t)r * DHEAD + c * 4);
    }
    for (int i = tid; i < BN * 32; i += THREADS) {
        int r = i >> 5, c = i & 31;
        cpa16(kh0 + r * KHP + c * 8, g_Mh + (size_t)r * DHEAD + c * 8);
    }
    cpa_commit();
    for (int i = tid; i < DHEAD; i += THREADS) wgs[i] = Wg[i];

    const bool evalmode = (isev[0] != 0);
    const int grow0 = qbase + strip * 16 + qr;
    const int grow1 = grow0 + 8;
    const float C0 = (evalmode && grow0 == 0) ? 0.f : CEXP2;  // eval row 0: s==0 -> P=1 exactly

    const int lg = lane >> 3;
    const int lr = lane & 7;
    unsigned kb1_sh = (unsigned)__cvta_generic_to_shared(kb1);
    unsigned kh0_sh = (unsigned)__cvta_generic_to_shared(kh0);
    unsigned kh1_sh = (unsigned)__cvta_generic_to_shared(kh1);
    unsigned Pb_sh  = (unsigned)__cvta_generic_to_shared(Pb);
    unsigned aBrow  = (hf * 32 + lr) * KHPB + lg * 16u;       // f16 K-frag row base

    // ---- wait for Q planes (group 1), build resident f16 A-frags (hi + lo) ----
    cpa_wait1();
    __syncthreads();
    unsigned aregH[16][4], aregL[16][4];     // 16 k16-chunks x 4 regs x 2 planes = 128 regs
    {
        unsigned base = kb1_sh + (strip * 16 + (lg & 1) * 8 + lr) * KHPB + (lg >> 1) * 16u;
        #pragma unroll
        for (int j = 0; j < 16; j++)
            ldsm4(base + j * 32u, aregH[j][0], aregH[j][1], aregH[j][2], aregH[j][3]);
        base += BM * KHPB;                   // Ql plane offset
        #pragma unroll
        for (int j = 0; j < 16; j++)
            ldsm4(base + j * 32u, aregL[j][0], aregL[j][1], aregL[j][2], aregL[j][3]);
    }

    // O accumulator: warp owns O[all 64 rows][n-slice warp*32 .. +32)
    float o[4][4][4];
    #pragma unroll
    for (int mt = 0; mt < 4; mt++)
        #pragma unroll
        for (int nt = 0; nt < 4; nt++)
            { o[mt][nt][0]=0.f; o[mt][nt][1]=0.f; o[mt][nt][2]=0.f; o[mt][nt][3]=0.f; }
    float l0 = 0.f, l1 = 0.f;                // per-lane partial row sums (reduced in epilogue)

    const int ntiles = nrows / BN;

    for (int jb = 0; jb < ntiles; jb++) {
        cpa_wait0();
        __syncthreads();                     // tile jb ready; prev tile fully consumed
        float* kb = (jb & 1) ? kb1 : kb0;
        unsigned kh_sh = (jb & 1) ? kh1_sh : kh0_sh;

        if (jb + 1 < ntiles) {               // prefetch next tile -> other buffers
            float*  kn  = (jb & 1) ? kb0 : kb1;
            __half* khn = (jb & 1) ? kh0 : kh1;
            const float*  src  = Mm   + (size_t)(jb + 1) * BN * DHEAD;
            const __half* srcH = g_Mh + (size_t)(jb + 1) * BN * DHEAD;
            for (int i = tid; i < BN * 64; i += THREADS) {
                int r = i >> 6, c = i & 63;
                cpa16(kn + r * SSTRIDE + c * 4, src + (size_t)r * DHEAD + c * 4);
            }
            for (int i = tid; i < BN * 32; i += THREADS) {
                int r = i >> 5, c = i & 31;
                cpa16(khn + r * KHP + c * 8, srcH + (size_t)r * DHEAD + c * 8);
            }
            cpa_commit();
        }

        // ---- GEMM1 (f16, 2-term): S'[strip rows][hf keys] = (Qh+Ql) . Kh^T  (log2 domain) ----
        float s[4][4];
        #pragma unroll
        for (int t = 0; t < 4; t++) { s[t][0]=0.f; s[t][1]=0.f; s[t][2]=0.f; s[t][3]=0.f; }
        unsigned aB = kh_sh + aBrow;
        #pragma unroll
        for (int jj = 0; jj < 8; jj++) {     // 32 dims (2 k16 chunks) per step
            #pragma unroll
            for (int t = 0; t < 4; t++) {
                unsigned b0, b1, b2, b3;
                ldsm4(aB + t * (8u * KHPB) + jj * 64u, b0, b1, b2, b3);
                mma16(s[t], aregH[2*jj],   b0, b1);
                mma16(s[t], aregL[2*jj],   b0, b1);
                mma16(s[t], aregH[2*jj+1], b2, b3);
                mma16(s[t], aregL[2*jj+1], b2, b3);
            }
        }

        // ---- mask (training: zero diag; eval: zero query row 0) ----
        int colbase = jb * BN + hf * 32 + 2 * qc;
        if (!evalmode) {
            #pragma unroll
            for (int t = 0; t < 4; t++) {
                int c0 = colbase + t * 8;
                if (c0     == grow0) s[t][0] = 0.f;
                if (c0 + 1 == grow0) s[t][1] = 0.f;
                if (c0     == grow1) s[t][2] = 0.f;
                if (c0 + 1 == grow1) s[t][3] = 0.f;
            }
        } else if (grow0 == 0) {
            #pragma unroll
            for (int t = 0; t < 4; t++) { s[t][0] = 0.f; s[t][1] = 0.f; }
        }

        // ---- P = exp2(s' - C), accumulate per-lane row-sum partials (no shuffles) ----
        #pragma unroll
        for (int t = 0; t < 4; t++) {
            s[t][0] = exp2f(s[t][0] - C0);
            s[t][1] = exp2f(s[t][1] - C0);
            s[t][2] = exp2f(s[t][2] - CEXP2);
            s[t][3] = exp2f(s[t][3] - CEXP2);
            l0 += s[t][0] + s[t][1];
            l1 += s[t][2] + s[t][3];
        }

        // ---- write P to exchange buffer ----
        {
            float* pr0 = Pb + (strip * 16 + qr) * PSTR + hf * 32 + 2 * qc;
            float* pr1 = pr0 + 8 * PSTR;
            #pragma unroll
            for (int t = 0; t < 4; t++) {
                *(float2*)(pr0 + t * 8) = make_float2(s[t][0], s[t][1]);
                *(float2*)(pr1 + t * 8) = make_float2(s[t][2], s[t][3]);
            }
        }
        __syncthreads();                     // P complete for all 64 rows x 64 keys

        // ---- GEMM2 (tf32): O[64 rows][warp n-slice 32] += P . V  (R15 scheduling) ----
        const unsigned* kbu = (const unsigned*)kb;
        unsigned aP = Pb_sh + (((lg & 1) * 8 + lr) * PSTR) * 4u + (lg >> 1) * 16u;
        #pragma unroll
        for (int kp = 0; kp < 4; kp++) {     // 16 keys per step
            unsigned vv[4][4];
            #pragma unroll
            for (int nt = 0; nt < 4; nt++) {
                int col = warp * 32 + nt * 8 + qr;
                vv[nt][0] = kbu[(kp * 16 + qc)      * SSTRIDE + col];
                vv[nt][1] = kbu[(kp * 16 + qc + 4)  * SSTRIDE + col];
                vv[nt][2] = kbu[(kp * 16 + qc + 8)  * SSTRIDE + col];
                vv[nt][3] = kbu[(kp * 16 + qc + 12) * SSTRIDE + col];
            }
            #pragma unroll
            for (int mt = 0; mt < 4; mt++) {
                unsigned pl0, pl1, pl2, pl3, ph0, ph1, ph2, ph3;
                unsigned base = aP + mt * (16u * PSTR * 4u) + kp * 64u;
                ldsm4(base,       pl0, pl1, pl2, pl3);
                ldsm4(base + 32u, ph0, ph1, ph2, ph3);
                #pragma unroll
                for (int nt = 0; nt < 4; nt++) {
                    mma8u(o[mt][nt], pl0, pl1, pl2, pl3, vv[nt][0], vv[nt][1]);
                    mma8u(o[mt][nt], ph0, ph1, ph2, ph3, vv[nt][2], vv[nt][3]);
                }
            }
        }
    }

    // ---- epilogue ----
    __syncthreads();
    l0 += __shfl_xor_sync(0xffffffffu, l0, 1);
    l0 += __shfl_xor_sync(0xffffffffu, l0, 2);
    l1 += __shfl_xor_sync(0xffffffffu, l1, 1);
    l1 += __shfl_xor_sync(0xffffffffu, l1, 2);
    if (qc == 0) {
        lpart[hf * BM + strip * 16 + qr]     = l0;
        lpart[hf * BM + strip * 16 + qr + 8] = l1;
    }
    __syncthreads();

    float gp[4][2];
    #pragma unroll
    for (int mt = 0; mt < 4; mt++) {
        int r0 = mt * 16 + qr, r1 = r0 + 8;
        float inv0 = 1.f / (lpart[r0] + lpart[BM + r0]);
        float inv1 = 1.f / (lpart[r1] + lpart[BM + r1]);
        float g0 = 0.f, g1 = 0.f;
        #pragma unroll
        for (int nt = 0; nt < 4; nt++) {
            int c0 = warp * 32 + nt * 8 + 2 * qc;
            o[mt][nt][0] *= inv0; o[mt][nt][1] *= inv0;
            o[mt][nt][2] *= inv1; o[mt][nt][3] *= inv1;
            g0 += o[mt][nt][0] * wgs[c0] + o[mt][nt][1] * wgs[c0 + 1];
            g1 += o[mt][nt][2] * wgs[c0] + o[mt][nt][3] * wgs[c0 + 1];
        }
        g0 += __shfl_xor_sync(0xffffffffu, g0, 1);
        g0 += __shfl_xor_sync(0xffffffffu, g0, 2);
        g1 += __shfl_xor_sync(0xffffffffu, g1, 1);
        g1 += __shfl_xor_sync(0xffffffffu, g1, 2);
        gp[mt][0] = g0; gp[mt][1] = g1;
    }
    if (qc == 0) {
        #pragma unroll
        for (int mt = 0; mt < 4; mt++) {
            gpart[warp * BM + mt * 16 + qr]     = gp[mt][0];
            gpart[warp * BM + mt * 16 + qr + 8] = gp[mt][1];
        }
    }
    __syncthreads();

    float gb = bgp[0] + gbp[0];
    #pragma unroll
    for (int mt = 0; mt < 4; mt++) {
        int r0 = mt * 16 + qr, r1 = r0 + 8;
        float sg0 = 0.f, sg1 = 0.f;
        #pragma unroll
        for (int ww = 0; ww < 8; ww++) { sg0 += gpart[ww * BM + r0]; sg1 += gpart[ww * BM + r1]; }
        float gate0 = 1.f / (1.f + __expf(-(sg0 + gb)));
        float gate1 = 1.f / (1.f + __expf(-(sg1 + gb)));
        float* orow0 = out + (size_t)(qbase + r0) * DHEAD;
        float* orow1 = out + (size_t)(qbase + r1) * DHEAD;
        const float* nrow0 = Nm + (size_t)(qbase + r0) * DHEAD;
        const float* nrow1 = Nm + (size_t)(qbase + r1) * DHEAD;
        #pragma unroll
        for (int nt = 0; nt < 4; nt++) {
            int c0 = warp * 32 + nt * 8 + 2 * qc;
            float2 nres0 = *(const float2*)(nrow0 + c0);
            float2 nres1 = *(const float2*)(nrow1 + c0);
            float2 w0, w1;
            w0.x = o[mt][nt][0] * gate0 + nres0.x * (1.f - gate0);
            w0.y = o[mt][nt][1] * gate0 + nres0.y * (1.f - gate0);
            w1.x = o[mt][nt][2] * gate1 + nres1.x * (1.f - gate1);
            w1.y = o[mt][nt][3] * gate1 + nres1.y * (1.f - gate1);
            *(float2*)(orow0 + c0) = w0;
            *(float2*)(orow1 + c0) = w1;
        }
    }
}

extern "C" void kernel_launch(void* const* d_in, const int* in_sizes, int n_in,
                              void* d_out, int out_size) {
    const float* Mm  = (const float*)d_in[0];
    const float* Nm  = (const float*)d_in[1];
    const float* Wg  = (const float*)d_in[2];
    const float* bg  = (const float*)d_in[3];
    const float* gbv = (const float*)d_in[4];
    const int*   ise = (const int*)  d_in[5];
    int nrows = in_sizes[0] / DHEAD;                      // 8192
    int total = nrows * DHEAD;

    convert_kernel<<<(total / 2 + 255) / 256, 256>>>(Mm, Nm, total);

    size_t smem = (size_t)(2 * KSZ + 2 * KHSZF + PSZ + DHEAD + 2 * BM + 8 * BM)
                  * sizeof(float);                        // ~220.5 KB
    cudaFuncSetAttribute(attn_matcher_kernel,
                         cudaFuncAttributeMaxDynamicSharedMemorySize, (int)smem);
    attn_matcher_kernel<<<nrows / BM, THREADS, smem>>>(Mm, Nm, Wg, bg, gbv, ise,
                                                       (float*)d_out, nrows);
}